// round 15
// baseline (speedup 1.0000x reference)
#include <cuda_runtime.h>
#include <cuda_bf16.h>
#include <math.h>
#include <cstdint>

// Problem constants
#define T_DIM   1024
#define B_DIM   8
#define INDIM   512
#define M_TOT   (T_DIM*B_DIM)   // 8192 rows (t,b)
#define NCH     128          // chunks for log-cumsum (chunk = 8 t)
#define TCHK    8            // t per chunk
#define NSEG    32           // segments for the S scan
#define SEGT    32           // t per segment (= 4 chunks)
#define NOUT    192

#define LOG_EPS (-18.420680743952367f)   // logf(1e-8f)

// ---------------- device scratch (no allocations allowed) ----------------
__device__ float g_v [M_TOT*64];       // (t*8+b)*64 + d
__device__ float g_k [M_TOT*64];
__device__ float g_la[M_TOT*64];       // log(max(sigmoid(a),eps))
__device__ float g_carry[NCH*512];     // exclusive prefix of chunk sums
__device__ float g_inv[512];           // 1/(exp(total)+1e-8)
__device__ float g_P[NSEG*B_DIM*64*64];  // segment sums -> exclusive prefix (4 MB)

// ---------------- helpers ----------------
__device__ __forceinline__ uint32_t cvt_bf16x2(float lo, float hi){
    uint32_t r;
    asm("cvt.rn.satfinite.bf16x2.f32 %0, %1, %2;" : "=r"(r) : "f"(hi), "f"(lo));
    return r;   // low 16 bits = lo
}
// m16n8k16 row.col bf16 MMA, fp32 accum (sm_80+, works on bare sm_103)
__device__ __forceinline__ void mma16816(float* c, const uint32_t* a, uint32_t b0, uint32_t b1){
    asm volatile(
        "mma.sync.aligned.m16n8k16.row.col.f32.bf16.bf16.f32 "
        "{%0,%1,%2,%3}, {%4,%5,%6,%7}, {%8,%9}, {%0,%1,%2,%3};"
        : "+f"(c[0]), "+f"(c[1]), "+f"(c[2]), "+f"(c[3])
        : "r"(a[0]), "r"(a[1]), "r"(a[2]), "r"(a[3]), "r"(b0), "r"(b1));
}

// ---------------- K1: mma.sync bf16-split projection GEMM ---------------------
// C[8192,192] = X[8192,512] @ W^T via Xh*Wh + Xh*Wl + Xl*Wh (fp32 accum).
// 64 CTAs x 256 threads; warp w owns rows w*16..w*16+15, all 192 cols.
#define KC   64
#define NCHK (INDIM/KC)     // 8
#define SA   72             // bf16 row stride (36 words == 4 mod 32: conflict-free frags)
#define OFF_AH   0
#define OFF_AL   18432      // 128*72*2
#define OFF_BH   36864
#define OFF_BL   64512      // +192*72*2
#define OFF_BIAS 92160
#define SMEM_PROJ (92160 + 192*4)

__global__ void __launch_bounds__(256) proj_mma(
    const float* __restrict__ x,
    const float* __restrict__ Wv, const float* __restrict__ bv,
    const float* __restrict__ Wk, const float* __restrict__ bk,
    const float* __restrict__ Wa, const float* __restrict__ ba)
{
    extern __shared__ char smem[];
    uint16_t* sAH = (uint16_t*)(smem + OFF_AH);
    uint16_t* sAL = (uint16_t*)(smem + OFF_AL);
    uint16_t* sBH = (uint16_t*)(smem + OFF_BH);
    uint16_t* sBL = (uint16_t*)(smem + OFF_BL);
    float*  sBias = (float*)(smem + OFF_BIAS);

    int tid = threadIdx.x;
    int wid = tid >> 5, lid = tid & 31;
    int g = lid >> 2, t = lid & 3;
    int mb = blockIdx.x * 128;
    if (tid < NOUT)
        sBias[tid] = (tid < 64) ? bv[tid] : ((tid < 128) ? bk[tid-64] : ba[tid-128]);

    float c[24][4];
    #pragma unroll
    for (int j = 0; j < 24; j++)
        #pragma unroll
        for (int q = 0; q < 4; q++) c[j][q] = 0.0f;

    for (int ch = 0; ch < NCHK; ch++){
        int kk = ch * KC;
        // ---- A fill: 128 rows x 16 float4 (8 iters/thread) ----
        #pragma unroll
        for (int it = 0; it < 8; it++){
            int i = tid + it*256;
            int row = i >> 4, q = i & 15;
            float4 xv = *(const float4*)&x[(mb + row)*INDIM + kk + q*4];
            uint32_t h01 = cvt_bf16x2(xv.x, xv.y);
            uint32_t h23 = cvt_bf16x2(xv.z, xv.w);
            float f0 = __uint_as_float(h01 << 16);
            float f1 = __uint_as_float(h01 & 0xFFFF0000u);
            float f2 = __uint_as_float(h23 << 16);
            float f3 = __uint_as_float(h23 & 0xFFFF0000u);
            uint32_t l01 = cvt_bf16x2(xv.x - f0, xv.y - f1);
            uint32_t l23 = cvt_bf16x2(xv.z - f2, xv.w - f3);
            int off = row*SA + q*4;
            *(uint2*)&sAH[off] = make_uint2(h01, h23);
            *(uint2*)&sAL[off] = make_uint2(l01, l23);
        }
        // ---- B fill: 192 rows x 16 float4 (12 iters/thread) ----
        #pragma unroll
        for (int it = 0; it < 12; it++){
            int i = tid + it*256;
            int row = i >> 4, q = i & 15;
            const float* W = (row < 64) ? &Wv[row*INDIM] :
                             (row < 128) ? &Wk[(row-64)*INDIM] : &Wa[(row-128)*INDIM];
            float4 wv = *(const float4*)&W[kk + q*4];
            uint32_t h01 = cvt_bf16x2(wv.x, wv.y);
            uint32_t h23 = cvt_bf16x2(wv.z, wv.w);
            float f0 = __uint_as_float(h01 << 16);
            float f1 = __uint_as_float(h01 & 0xFFFF0000u);
            float f2 = __uint_as_float(h23 << 16);
            float f3 = __uint_as_float(h23 & 0xFFFF0000u);
            uint32_t l01 = cvt_bf16x2(wv.x - f0, wv.y - f1);
            uint32_t l23 = cvt_bf16x2(wv.z - f2, wv.w - f3);
            int off = row*SA + q*4;
            *(uint2*)&sBH[off] = make_uint2(h01, h23);
            *(uint2*)&sBL[off] = make_uint2(l01, l23);
        }
        __syncthreads();
        // ---- MMA: 4 K=16 steps, 24 n-tiles, 3 split products each ----
        #pragma unroll
        for (int ks = 0; ks < 4; ks++){
            int ak = ks*16;
            int ra = (wid*16 + g)*SA + ak + 2*t;
            uint32_t aH[4], aL[4];
            aH[0] = *(const uint32_t*)&sAH[ra];
            aH[1] = *(const uint32_t*)&sAH[ra + 8*SA];
            aH[2] = *(const uint32_t*)&sAH[ra + 8];
            aH[3] = *(const uint32_t*)&sAH[ra + 8*SA + 8];
            aL[0] = *(const uint32_t*)&sAL[ra];
            aL[1] = *(const uint32_t*)&sAL[ra + 8*SA];
            aL[2] = *(const uint32_t*)&sAL[ra + 8];
            aL[3] = *(const uint32_t*)&sAL[ra + 8*SA + 8];
            #pragma unroll
            for (int j = 0; j < 24; j++){
                int rb = (j*8 + g)*SA + ak + 2*t;
                uint32_t bH0 = *(const uint32_t*)&sBH[rb];
                uint32_t bH1 = *(const uint32_t*)&sBH[rb + 8];
                uint32_t bL0 = *(const uint32_t*)&sBL[rb];
                uint32_t bL1 = *(const uint32_t*)&sBL[rb + 8];
                mma16816(c[j], aH, bH0, bH1);
                mma16816(c[j], aH, bL0, bL1);
                mma16816(c[j], aL, bH0, bH1);
            }
        }
        __syncthreads();
    }

    // ---- epilogue: bias + routing; c[j] covers rows (row0,row0+8), cols j*8+2t..+1
    int row0 = mb + wid*16 + g;
    #pragma unroll
    for (int j = 0; j < 24; j++){
        float b0 = sBias[j*8 + 2*t];
        float b1 = sBias[j*8 + 2*t + 1];
        float v00 = c[j][0] + b0, v01 = c[j][1] + b1;    // row0
        float v10 = c[j][2] + b0, v11 = c[j][3] + b1;    // row0+8
        int col = (j & 7)*8 + 2*t;
        if (j < 8){
            *(float2*)&g_v[row0*64 + col]     = make_float2(v00, v01);
            *(float2*)&g_v[(row0+8)*64 + col] = make_float2(v10, v11);
        } else if (j < 16){
            *(float2*)&g_k[row0*64 + col]     = make_float2(v00, v01);
            *(float2*)&g_k[(row0+8)*64 + col] = make_float2(v10, v11);
        } else {
            float s00 = fmaxf(fminf(v00,0.0f) - log1pf(expf(-fabsf(v00))), LOG_EPS);
            float s01 = fmaxf(fminf(v01,0.0f) - log1pf(expf(-fabsf(v01))), LOG_EPS);
            float s10 = fmaxf(fminf(v10,0.0f) - log1pf(expf(-fabsf(v10))), LOG_EPS);
            float s11 = fmaxf(fminf(v11,0.0f) - log1pf(expf(-fabsf(v11))), LOG_EPS);
            *(float2*)&g_la[row0*64 + col]     = make_float2(s00, s01);
            *(float2*)&g_la[(row0+8)*64 + col] = make_float2(s10, s11);
        }
    }
}

// ---------------- K2: fused chunk sums + exclusive prefix (coalesced) ---------
__global__ void __launch_bounds__(1024) la_scan(){
    __shared__ float tile[32][33];
    int lane = threadIdx.x & 31;
    int wid  = threadIdx.x >> 5;
    int bnBase = blockIdx.x * 32;
    int myBn = bnBase + wid;
    float carry = 0.0f;
    #pragma unroll
    for (int pass = 0; pass < NCH/32; pass++){
        int c = pass*32 + wid;
        const float* p = g_la + c*TCHK*512 + bnBase + lane;
        float s = 0.0f;
        #pragma unroll
        for (int i = 0; i < TCHK; i++) s += p[i*512];
        tile[wid][lane] = s;
        __syncthreads();
        float v = tile[lane][wid];
        float sc = v;
        #pragma unroll
        for (int off = 1; off < 32; off <<= 1){
            float t = __shfl_up_sync(0xffffffffu, sc, off);
            if (lane >= off) sc += t;
        }
        float ex = __shfl_up_sync(0xffffffffu, sc, 1);
        if (lane == 0) ex = 0.0f;
        float tot = __shfl_sync(0xffffffffu, sc, 31);
        __syncthreads();
        tile[lane][wid] = carry + ex;
        carry += tot;
        __syncthreads();
        g_carry[(pass*32 + wid)*512 + bnBase + lane] = tile[wid][lane];
        __syncthreads();
    }
    if (lane == 31) g_inv[myBn] = 1.0f / (expf(carry) + 1e-8f);
}

// ---------------- shared fill: v tile + computed kd tile ----------------------
__device__ __forceinline__ void fill_tiles(float* s_v, float* s_kd, int seg, int b, int tid){
    #pragma unroll
    for (int i = tid; i < SEGT*16; i += 256){
        int t = i >> 4, q = i & 15;
        int row = ((seg*SEGT + t)*B_DIM + b)*64;
        ((float4*)s_v)[i] = *(const float4*)&g_v[row + q*4];
    }
    {
        int n  = tid & 63;
        int cl = tid >> 6;
        int c  = seg*4 + cl;
        int bn = b*64 + n;
        float cum = g_carry[c*512 + bn];
        float inv = g_inv[bn];
        #pragma unroll
        for (int i = 0; i < TCHK; i++){
            int t = cl*TCHK + i;
            int addr = ((seg*SEGT + t)*B_DIM + b)*64 + n;
            cum += g_la[addr];
            float dec = expf(cum) * inv;
            s_kd[t*64 + n] = g_k[addr] * dec;
        }
    }
    __syncthreads();
}

// ---------------- K4: per-segment outer-product sums ----------
__global__ void __launch_bounds__(256) seg_sums(){
    int seg = blockIdx.x, b = blockIdx.y;
    __shared__ float s_v[SEGT*64];
    __shared__ float s_kd[SEGT*64];
    int tid = threadIdx.x;
    fill_tiles(s_v, s_kd, seg, b, tid);
    int dq = tid >> 4, n4 = tid & 15;
    float4 a0 = {0,0,0,0}, a1 = {0,0,0,0}, a2 = {0,0,0,0}, a3 = {0,0,0,0};
    #pragma unroll 4
    for (int t = 0; t < SEGT; t++){
        float4 kd = *(const float4*)&s_kd[t*64 + n4*4];
        float4 vv = *(const float4*)&s_v [t*64 + dq*4];
        a0.x = fmaf(vv.x, kd.x, a0.x); a0.y = fmaf(vv.x, kd.y, a0.y);
        a0.z = fmaf(vv.x, kd.z, a0.z); a0.w = fmaf(vv.x, kd.w, a0.w);
        a1.x = fmaf(vv.y, kd.x, a1.x); a1.y = fmaf(vv.y, kd.y, a1.y);
        a1.z = fmaf(vv.y, kd.z, a1.z); a1.w = fmaf(vv.y, kd.w, a1.w);
        a2.x = fmaf(vv.z, kd.x, a2.x); a2.y = fmaf(vv.z, kd.y, a2.y);
        a2.z = fmaf(vv.z, kd.z, a2.z); a2.w = fmaf(vv.z, kd.w, a2.w);
        a3.x = fmaf(vv.w, kd.x, a3.x); a3.y = fmaf(vv.w, kd.y, a3.y);
        a3.z = fmaf(vv.w, kd.z, a3.z); a3.w = fmaf(vv.w, kd.w, a3.w);
    }
    float* P = g_P + (seg*B_DIM + b)*4096;
    *(float4*)&P[(dq*4+0)*64 + n4*4] = a0;
    *(float4*)&P[(dq*4+1)*64 + n4*4] = a1;
    *(float4*)&P[(dq*4+2)*64 + n4*4] = a2;
    *(float4*)&P[(dq*4+3)*64 + n4*4] = a3;
}

// ---------------- K4b: exclusive prefix of P along seg (transpose warp-scan) --
// 1024 blocks x 1024 threads; block owns 32 consecutive idx x all 32 segs.
// Loads/stores coalesced along idx; scan order over segs identical to serial.
__global__ void __launch_bounds__(1024) seg_prefix(){
    __shared__ float tile[32][33];
    int lane = threadIdx.x & 31;
    int wid  = threadIdx.x >> 5;          // seg for load/store
    int idxBase = blockIdx.x * 32;
    tile[wid][lane] = g_P[wid*32768 + idxBase + lane];
    __syncthreads();
    // warp 'wid' scans segs for idx = idxBase + wid: seg index = lane
    float sc = tile[lane][wid];
    #pragma unroll
    for (int off = 1; off < 32; off <<= 1){
        float t = __shfl_up_sync(0xffffffffu, sc, off);
        if (lane >= off) sc += t;
    }
    float ex = __shfl_up_sync(0xffffffffu, sc, 1);
    if (lane == 0) ex = 0.0f;
    __syncthreads();
    tile[lane][wid] = ex;
    __syncthreads();
    g_P[wid*32768 + idxBase + lane] = tile[wid][lane];
}

// ---------------- K5: scan + store (128 MB) ---------------------
__global__ void __launch_bounds__(256) scan_kernel(float* __restrict__ out){
    int seg = blockIdx.x, b = blockIdx.y;
    __shared__ float s_v[SEGT*64];
    __shared__ float s_kd[SEGT*64];
    int tid = threadIdx.x;
    fill_tiles(s_v, s_kd, seg, b, tid);
    int dq = tid >> 4, n4 = tid & 15;
    const float* P = g_P + (seg*B_DIM + b)*4096;
    float4 a0 = *(const float4*)&P[(dq*4+0)*64 + n4*4];
    float4 a1 = *(const float4*)&P[(dq*4+1)*64 + n4*4];
    float4 a2 = *(const float4*)&P[(dq*4+2)*64 + n4*4];
    float4 a3 = *(const float4*)&P[(dq*4+3)*64 + n4*4];
    #pragma unroll 4
    for (int t = 0; t < SEGT; t++){
        float4 kd = *(const float4*)&s_kd[t*64 + n4*4];
        float4 vv = *(const float4*)&s_v [t*64 + dq*4];
        a0.x = fmaf(vv.x, kd.x, a0.x); a0.y = fmaf(vv.x, kd.y, a0.y);
        a0.z = fmaf(vv.x, kd.z, a0.z); a0.w = fmaf(vv.x, kd.w, a0.w);
        a1.x = fmaf(vv.y, kd.x, a1.x); a1.y = fmaf(vv.y, kd.y, a1.y);
        a1.z = fmaf(vv.y, kd.z, a1.z); a1.w = fmaf(vv.y, kd.w, a1.w);
        a2.x = fmaf(vv.z, kd.x, a2.x); a2.y = fmaf(vv.z, kd.y, a2.y);
        a2.z = fmaf(vv.z, kd.z, a2.z); a2.w = fmaf(vv.z, kd.w, a2.w);
        a3.x = fmaf(vv.w, kd.x, a3.x); a3.y = fmaf(vv.w, kd.y, a3.y);
        a3.z = fmaf(vv.w, kd.z, a3.z); a3.w = fmaf(vv.w, kd.w, a3.w);
        float* orow = out + (size_t)((seg*SEGT + t)*B_DIM + b)*4096;
        *(float4*)&orow[(dq*4+0)*64 + n4*4] = a0;
        *(float4*)&orow[(dq*4+1)*64 + n4*4] = a1;
        *(float4*)&orow[(dq*4+2)*64 + n4*4] = a2;
        *(float4*)&orow[(dq*4+3)*64 + n4*4] = a3;
    }
}

// ---------------- launch ----------------
extern "C" void kernel_launch(void* const* d_in, const int* in_sizes, int n_in,
                              void* d_out, int out_size){
    const float* x  = (const float*)d_in[0];
    const float* Wv = (const float*)d_in[1];
    const float* bv = (const float*)d_in[2];
    const float* Wk = (const float*)d_in[3];
    const float* bk = (const float*)d_in[4];
    const float* Wa = (const float*)d_in[5];
    const float* ba = (const float*)d_in[6];
    float* out = (float*)d_out;

    static int attr_set = 0;
    if (!attr_set){
        cudaFuncSetAttribute(proj_mma, cudaFuncAttributeMaxDynamicSharedMemorySize, SMEM_PROJ);
        attr_set = 1;
    }
    proj_mma<<<M_TOT/128, 256, SMEM_PROJ>>>(x, Wv, bv, Wk, bk, Wa, ba);
    la_scan<<<16, 1024>>>();
    dim3 gseg(NSEG, B_DIM);
    seg_sums<<<gseg, 256>>>();
    seg_prefix<<<1024, 1024>>>();
    scan_kernel<<<gseg, 256>>>(out);
}

// round 16
// speedup vs baseline: 1.0319x; 1.0319x over previous
#include <cuda_runtime.h>
#include <cuda_bf16.h>
#include <math.h>
#include <cstdint>

// Problem constants
#define T_DIM   1024
#define B_DIM   8
#define INDIM   512
#define M_TOT   (T_DIM*B_DIM)   // 8192 rows (t,b)
#define NCH     128          // chunks for log-cumsum (chunk = 8 t)
#define TCHK    8            // t per chunk
#define NSEG    32           // segments for the S scan
#define SEGT    32           // t per segment (= 4 chunks)
#define NOUT    192

#define LOG_EPS (-18.420680743952367f)   // logf(1e-8f)

// ---------------- device scratch (no allocations allowed) ----------------
__device__ float g_v [M_TOT*64];       // (t*8+b)*64 + d
__device__ float g_k [M_TOT*64];
__device__ float g_la[M_TOT*64];       // log(max(sigmoid(a),eps))
__device__ float g_carry[NCH*512];     // exclusive prefix of chunk sums
__device__ float g_inv[512];           // 1/(exp(total)+1e-8)
__device__ float g_P[NSEG*B_DIM*64*64];  // segment sums -> exclusive prefix (4 MB)

// ---------------- helpers ----------------
__device__ __forceinline__ uint32_t cvt_bf16x2(float lo, float hi){
    uint32_t r;
    asm("cvt.rn.satfinite.bf16x2.f32 %0, %1, %2;" : "=r"(r) : "f"(hi), "f"(lo));
    return r;   // low 16 bits = lo
}
// m16n8k16 row.col bf16 MMA, fp32 accum (sm_80+, works on bare sm_103)
__device__ __forceinline__ void mma16816(float* c, const uint32_t* a, uint32_t b0, uint32_t b1){
    asm volatile(
        "mma.sync.aligned.m16n8k16.row.col.f32.bf16.bf16.f32 "
        "{%0,%1,%2,%3}, {%4,%5,%6,%7}, {%8,%9}, {%0,%1,%2,%3};"
        : "+f"(c[0]), "+f"(c[1]), "+f"(c[2]), "+f"(c[3])
        : "r"(a[0]), "r"(a[1]), "r"(a[2]), "r"(a[3]), "r"(b0), "r"(b1));
}

// ---------------- K1: mma.sync bf16-split projection GEMM ---------------------
// C[8192,192] = X[8192,512] @ W^T via Xh*Wh + Xh*Wl + Xl*Wh (fp32 accum).
// 64 CTAs x 256 threads; warp w owns rows w*16..w*16+15, all 192 cols.
#define KC   64
#define NCHK (INDIM/KC)     // 8
#define SA   72             // bf16 row stride (36 words == 4 mod 32: conflict-free frags)
#define OFF_AH   0
#define OFF_AL   18432      // 128*72*2
#define OFF_BH   36864
#define OFF_BL   64512      // +192*72*2
#define OFF_BIAS 92160
#define SMEM_PROJ (92160 + 192*4)

__global__ void __launch_bounds__(256) proj_mma(
    const float* __restrict__ x,
    const float* __restrict__ Wv, const float* __restrict__ bv,
    const float* __restrict__ Wk, const float* __restrict__ bk,
    const float* __restrict__ Wa, const float* __restrict__ ba)
{
    extern __shared__ char smem[];
    uint16_t* sAH = (uint16_t*)(smem + OFF_AH);
    uint16_t* sAL = (uint16_t*)(smem + OFF_AL);
    uint16_t* sBH = (uint16_t*)(smem + OFF_BH);
    uint16_t* sBL = (uint16_t*)(smem + OFF_BL);
    float*  sBias = (float*)(smem + OFF_BIAS);

    int tid = threadIdx.x;
    int wid = tid >> 5, lid = tid & 31;
    int g = lid >> 2, t = lid & 3;
    int mb = blockIdx.x * 128;
    if (tid < NOUT)
        sBias[tid] = (tid < 64) ? bv[tid] : ((tid < 128) ? bk[tid-64] : ba[tid-128]);

    float c[24][4];
    #pragma unroll
    for (int j = 0; j < 24; j++)
        #pragma unroll
        for (int q = 0; q < 4; q++) c[j][q] = 0.0f;

    for (int ch = 0; ch < NCHK; ch++){
        int kk = ch * KC;
        // ---- A fill: 128 rows x 16 float4 (8 iters/thread) ----
        #pragma unroll
        for (int it = 0; it < 8; it++){
            int i = tid + it*256;
            int row = i >> 4, q = i & 15;
            float4 xv = *(const float4*)&x[(mb + row)*INDIM + kk + q*4];
            uint32_t h01 = cvt_bf16x2(xv.x, xv.y);
            uint32_t h23 = cvt_bf16x2(xv.z, xv.w);
            float f0 = __uint_as_float(h01 << 16);
            float f1 = __uint_as_float(h01 & 0xFFFF0000u);
            float f2 = __uint_as_float(h23 << 16);
            float f3 = __uint_as_float(h23 & 0xFFFF0000u);
            uint32_t l01 = cvt_bf16x2(xv.x - f0, xv.y - f1);
            uint32_t l23 = cvt_bf16x2(xv.z - f2, xv.w - f3);
            int off = row*SA + q*4;
            *(uint2*)&sAH[off] = make_uint2(h01, h23);
            *(uint2*)&sAL[off] = make_uint2(l01, l23);
        }
        // ---- B fill: 192 rows x 16 float4 (12 iters/thread) ----
        #pragma unroll
        for (int it = 0; it < 12; it++){
            int i = tid + it*256;
            int row = i >> 4, q = i & 15;
            const float* W = (row < 64) ? &Wv[row*INDIM] :
                             (row < 128) ? &Wk[(row-64)*INDIM] : &Wa[(row-128)*INDIM];
            float4 wv = *(const float4*)&W[kk + q*4];
            uint32_t h01 = cvt_bf16x2(wv.x, wv.y);
            uint32_t h23 = cvt_bf16x2(wv.z, wv.w);
            float f0 = __uint_as_float(h01 << 16);
            float f1 = __uint_as_float(h01 & 0xFFFF0000u);
            float f2 = __uint_as_float(h23 << 16);
            float f3 = __uint_as_float(h23 & 0xFFFF0000u);
            uint32_t l01 = cvt_bf16x2(wv.x - f0, wv.y - f1);
            uint32_t l23 = cvt_bf16x2(wv.z - f2, wv.w - f3);
            int off = row*SA + q*4;
            *(uint2*)&sBH[off] = make_uint2(h01, h23);
            *(uint2*)&sBL[off] = make_uint2(l01, l23);
        }
        __syncthreads();
        // ---- MMA: 4 K=16 steps, 24 n-tiles, 3 split products each ----
        #pragma unroll
        for (int ks = 0; ks < 4; ks++){
            int ak = ks*16;
            int ra = (wid*16 + g)*SA + ak + 2*t;
            uint32_t aH[4], aL[4];
            aH[0] = *(const uint32_t*)&sAH[ra];
            aH[1] = *(const uint32_t*)&sAH[ra + 8*SA];
            aH[2] = *(const uint32_t*)&sAH[ra + 8];
            aH[3] = *(const uint32_t*)&sAH[ra + 8*SA + 8];
            aL[0] = *(const uint32_t*)&sAL[ra];
            aL[1] = *(const uint32_t*)&sAL[ra + 8*SA];
            aL[2] = *(const uint32_t*)&sAL[ra + 8];
            aL[3] = *(const uint32_t*)&sAL[ra + 8*SA + 8];
            #pragma unroll
            for (int j = 0; j < 24; j++){
                int rb = (j*8 + g)*SA + ak + 2*t;
                uint32_t bH0 = *(const uint32_t*)&sBH[rb];
                uint32_t bH1 = *(const uint32_t*)&sBH[rb + 8];
                uint32_t bL0 = *(const uint32_t*)&sBL[rb];
                uint32_t bL1 = *(const uint32_t*)&sBL[rb + 8];
                mma16816(c[j], aH, bH0, bH1);
                mma16816(c[j], aH, bL0, bL1);
                mma16816(c[j], aL, bH0, bH1);
            }
        }
        __syncthreads();
    }

    // ---- epilogue: bias + routing; c[j] covers rows (row0,row0+8), cols j*8+2t..+1
    int row0 = mb + wid*16 + g;
    #pragma unroll
    for (int j = 0; j < 24; j++){
        float b0 = sBias[j*8 + 2*t];
        float b1 = sBias[j*8 + 2*t + 1];
        float v00 = c[j][0] + b0, v01 = c[j][1] + b1;    // row0
        float v10 = c[j][2] + b0, v11 = c[j][3] + b1;    // row0+8
        int col = (j & 7)*8 + 2*t;
        if (j < 8){
            *(float2*)&g_v[row0*64 + col]     = make_float2(v00, v01);
            *(float2*)&g_v[(row0+8)*64 + col] = make_float2(v10, v11);
        } else if (j < 16){
            *(float2*)&g_k[row0*64 + col]     = make_float2(v00, v01);
            *(float2*)&g_k[(row0+8)*64 + col] = make_float2(v10, v11);
        } else {
            float s00 = fmaxf(fminf(v00,0.0f) - log1pf(expf(-fabsf(v00))), LOG_EPS);
            float s01 = fmaxf(fminf(v01,0.0f) - log1pf(expf(-fabsf(v01))), LOG_EPS);
            float s10 = fmaxf(fminf(v10,0.0f) - log1pf(expf(-fabsf(v10))), LOG_EPS);
            float s11 = fmaxf(fminf(v11,0.0f) - log1pf(expf(-fabsf(v11))), LOG_EPS);
            *(float2*)&g_la[row0*64 + col]     = make_float2(s00, s01);
            *(float2*)&g_la[(row0+8)*64 + col] = make_float2(s10, s11);
        }
    }
}

// ---------------- K2: fused chunk sums + exclusive prefix (coalesced) ---------
__global__ void __launch_bounds__(1024) la_scan(){
    __shared__ float tile[32][33];
    int lane = threadIdx.x & 31;
    int wid  = threadIdx.x >> 5;
    int bnBase = blockIdx.x * 32;
    int myBn = bnBase + wid;
    float carry = 0.0f;
    #pragma unroll
    for (int pass = 0; pass < NCH/32; pass++){
        int c = pass*32 + wid;
        const float* p = g_la + c*TCHK*512 + bnBase + lane;
        float s = 0.0f;
        #pragma unroll
        for (int i = 0; i < TCHK; i++) s += p[i*512];
        tile[wid][lane] = s;
        __syncthreads();
        float v = tile[lane][wid];
        float sc = v;
        #pragma unroll
        for (int off = 1; off < 32; off <<= 1){
            float t = __shfl_up_sync(0xffffffffu, sc, off);
            if (lane >= off) sc += t;
        }
        float ex = __shfl_up_sync(0xffffffffu, sc, 1);
        if (lane == 0) ex = 0.0f;
        float tot = __shfl_sync(0xffffffffu, sc, 31);
        __syncthreads();
        tile[lane][wid] = carry + ex;
        carry += tot;
        __syncthreads();
        g_carry[(pass*32 + wid)*512 + bnBase + lane] = tile[wid][lane];
        __syncthreads();
    }
    if (lane == 31) g_inv[myBn] = 1.0f / (expf(carry) + 1e-8f);
}

// ---------------- shared fill: v tile + computed kd tile ----------------------
__device__ __forceinline__ void fill_tiles(float* s_v, float* s_kd, int seg, int b, int tid){
    #pragma unroll
    for (int i = tid; i < SEGT*16; i += 256){
        int t = i >> 4, q = i & 15;
        int row = ((seg*SEGT + t)*B_DIM + b)*64;
        ((float4*)s_v)[i] = *(const float4*)&g_v[row + q*4];
    }
    {
        int n  = tid & 63;
        int cl = tid >> 6;
        int c  = seg*4 + cl;
        int bn = b*64 + n;
        float cum = g_carry[c*512 + bn];
        float inv = g_inv[bn];
        #pragma unroll
        for (int i = 0; i < TCHK; i++){
            int t = cl*TCHK + i;
            int addr = ((seg*SEGT + t)*B_DIM + b)*64 + n;
            cum += g_la[addr];
            float dec = expf(cum) * inv;
            s_kd[t*64 + n] = g_k[addr] * dec;
        }
    }
    __syncthreads();
}

// ---------------- K4: per-segment outer-product sums ----------
__global__ void __launch_bounds__(256) seg_sums(){
    int seg = blockIdx.x, b = blockIdx.y;
    __shared__ float s_v[SEGT*64];
    __shared__ float s_kd[SEGT*64];
    int tid = threadIdx.x;
    fill_tiles(s_v, s_kd, seg, b, tid);
    int dq = tid >> 4, n4 = tid & 15;
    float4 a0 = {0,0,0,0}, a1 = {0,0,0,0}, a2 = {0,0,0,0}, a3 = {0,0,0,0};
    #pragma unroll 4
    for (int t = 0; t < SEGT; t++){
        float4 kd = *(const float4*)&s_kd[t*64 + n4*4];
        float4 vv = *(const float4*)&s_v [t*64 + dq*4];
        a0.x = fmaf(vv.x, kd.x, a0.x); a0.y = fmaf(vv.x, kd.y, a0.y);
        a0.z = fmaf(vv.x, kd.z, a0.z); a0.w = fmaf(vv.x, kd.w, a0.w);
        a1.x = fmaf(vv.y, kd.x, a1.x); a1.y = fmaf(vv.y, kd.y, a1.y);
        a1.z = fmaf(vv.y, kd.z, a1.z); a1.w = fmaf(vv.y, kd.w, a1.w);
        a2.x = fmaf(vv.z, kd.x, a2.x); a2.y = fmaf(vv.z, kd.y, a2.y);
        a2.z = fmaf(vv.z, kd.z, a2.z); a2.w = fmaf(vv.z, kd.w, a2.w);
        a3.x = fmaf(vv.w, kd.x, a3.x); a3.y = fmaf(vv.w, kd.y, a3.y);
        a3.z = fmaf(vv.w, kd.z, a3.z); a3.w = fmaf(vv.w, kd.w, a3.w);
    }
    float* P = g_P + (seg*B_DIM + b)*4096;
    *(float4*)&P[(dq*4+0)*64 + n4*4] = a0;
    *(float4*)&P[(dq*4+1)*64 + n4*4] = a1;
    *(float4*)&P[(dq*4+2)*64 + n4*4] = a2;
    *(float4*)&P[(dq*4+3)*64 + n4*4] = a3;
}

// ---------------- K4b: exclusive prefix of P along seg (register scan) --------
// 128 blocks x 256 threads; thread owns one idx, loads all 32 segs (independent
// -> MLP=32), scans in registers (same left-to-right order), stores coalesced.
__global__ void __launch_bounds__(256) seg_prefix(){
    int idx = blockIdx.x*256 + threadIdx.x;   // 0..32767
    float v[NSEG];
    #pragma unroll
    for (int s = 0; s < NSEG; s++) v[s] = g_P[s*32768 + idx];
    float carry = 0.0f;
    #pragma unroll
    for (int s = 0; s < NSEG; s++){
        float t = v[s];
        v[s] = carry;
        carry += t;
    }
    #pragma unroll
    for (int s = 0; s < NSEG; s++) g_P[s*32768 + idx] = v[s];
}

// ---------------- K5: scan + store (128 MB) ---------------------
__global__ void __launch_bounds__(256) scan_kernel(float* __restrict__ out){
    int seg = blockIdx.x, b = blockIdx.y;
    __shared__ float s_v[SEGT*64];
    __shared__ float s_kd[SEGT*64];
    int tid = threadIdx.x;
    fill_tiles(s_v, s_kd, seg, b, tid);
    int dq = tid >> 4, n4 = tid & 15;
    const float* P = g_P + (seg*B_DIM + b)*4096;
    float4 a0 = *(const float4*)&P[(dq*4+0)*64 + n4*4];
    float4 a1 = *(const float4*)&P[(dq*4+1)*64 + n4*4];
    float4 a2 = *(const float4*)&P[(dq*4+2)*64 + n4*4];
    float4 a3 = *(const float4*)&P[(dq*4+3)*64 + n4*4];
    #pragma unroll 4
    for (int t = 0; t < SEGT; t++){
        float4 kd = *(const float4*)&s_kd[t*64 + n4*4];
        float4 vv = *(const float4*)&s_v [t*64 + dq*4];
        a0.x = fmaf(vv.x, kd.x, a0.x); a0.y = fmaf(vv.x, kd.y, a0.y);
        a0.z = fmaf(vv.x, kd.z, a0.z); a0.w = fmaf(vv.x, kd.w, a0.w);
        a1.x = fmaf(vv.y, kd.x, a1.x); a1.y = fmaf(vv.y, kd.y, a1.y);
        a1.z = fmaf(vv.y, kd.z, a1.z); a1.w = fmaf(vv.y, kd.w, a1.w);
        a2.x = fmaf(vv.z, kd.x, a2.x); a2.y = fmaf(vv.z, kd.y, a2.y);
        a2.z = fmaf(vv.z, kd.z, a2.z); a2.w = fmaf(vv.z, kd.w, a2.w);
        a3.x = fmaf(vv.w, kd.x, a3.x); a3.y = fmaf(vv.w, kd.y, a3.y);
        a3.z = fmaf(vv.w, kd.z, a3.z); a3.w = fmaf(vv.w, kd.w, a3.w);
        float* orow = out + (size_t)((seg*SEGT + t)*B_DIM + b)*4096;
        *(float4*)&orow[(dq*4+0)*64 + n4*4] = a0;
        *(float4*)&orow[(dq*4+1)*64 + n4*4] = a1;
        *(float4*)&orow[(dq*4+2)*64 + n4*4] = a2;
        *(float4*)&orow[(dq*4+3)*64 + n4*4] = a3;
    }
}

// ---------------- launch ----------------
extern "C" void kernel_launch(void* const* d_in, const int* in_sizes, int n_in,
                              void* d_out, int out_size){
    const float* x  = (const float*)d_in[0];
    const float* Wv = (const float*)d_in[1];
    const float* bv = (const float*)d_in[2];
    const float* Wk = (const float*)d_in[3];
    const float* bk = (const float*)d_in[4];
    const float* Wa = (const float*)d_in[5];
    const float* ba = (const float*)d_in[6];
    float* out = (float*)d_out;

    static int attr_set = 0;
    if (!attr_set){
        cudaFuncSetAttribute(proj_mma, cudaFuncAttributeMaxDynamicSharedMemorySize, SMEM_PROJ);
        attr_set = 1;
    }
    proj_mma<<<M_TOT/128, 256, SMEM_PROJ>>>(x, Wv, bv, Wk, bk, Wa, ba);
    la_scan<<<16, 1024>>>();
    dim3 gseg(NSEG, B_DIM);
    seg_sums<<<gseg, 256>>>();
    seg_prefix<<<128, 256>>>();
    scan_kernel<<<gseg, 256>>>(out);
}

// round 17
// speedup vs baseline: 1.1524x; 1.1168x over previous
#include <cuda_runtime.h>
#include <cuda_bf16.h>
#include <math.h>
#include <cstdint>

// Problem constants
#define T_DIM   1024
#define B_DIM   8
#define INDIM   512
#define M_TOT   (T_DIM*B_DIM)   // 8192 rows (t,b)
#define NCH     128          // chunks for log-cumsum (chunk = 8 t)
#define TCHK    8            // t per chunk
#define NSEG    32           // segments for the S scan
#define SEGT    32           // t per segment (= 4 chunks)
#define NOUT    192

#define LOG_EPS (-18.420680743952367f)   // logf(1e-8f)

// ---------------- device scratch (no allocations allowed) ----------------
__device__ float    g_v [M_TOT*64];       // (t*8+b)*64 + d
__device__ float    g_k [M_TOT*64];
__device__ float    g_la[M_TOT*64];       // log(max(sigmoid(a),eps))
__device__ float    g_carry[NCH*512];     // exclusive prefix of chunk sums
__device__ float    g_inv[512];           // 1/(exp(total)+1e-8)
__device__ float    g_P[NSEG*B_DIM*64*64];  // segment sums -> exclusive prefix (4 MB)
__device__ uint16_t g_Wh[NOUT*INDIM];     // W hi bf16 [row][k]
__device__ uint16_t g_Wl[NOUT*INDIM];     // W lo bf16

// ---------------- helpers ----------------
__device__ __forceinline__ uint32_t cvt_bf16x2(float lo, float hi){
    uint32_t r;
    asm("cvt.rn.satfinite.bf16x2.f32 %0, %1, %2;" : "=r"(r) : "f"(hi), "f"(lo));
    return r;   // low 16 bits = lo
}
// m16n8k16 row.col bf16 MMA, fp32 accum (sm_80+, works on bare sm_103)
__device__ __forceinline__ void mma16816(float* c, const uint32_t* a, uint32_t b0, uint32_t b1){
    asm volatile(
        "mma.sync.aligned.m16n8k16.row.col.f32.bf16.bf16.f32 "
        "{%0,%1,%2,%3}, {%4,%5,%6,%7}, {%8,%9}, {%0,%1,%2,%3};"
        : "+f"(c[0]), "+f"(c[1]), "+f"(c[2]), "+f"(c[3])
        : "r"(a[0]), "r"(a[1]), "r"(a[2]), "r"(a[3]), "r"(b0), "r"(b1));
}

// ---------------- K0: pack W into bf16 hi/lo (once, not per CTA) ---------------
// 24576 threads, each converts 4 elements (same per-element ops as old B fill).
__global__ void __launch_bounds__(256) pack_w(
    const float* __restrict__ Wv, const float* __restrict__ Wk, const float* __restrict__ Wa)
{
    int i = blockIdx.x*256 + threadIdx.x;   // 0..24575
    int j = i >> 7;          // row 0..191
    int q = i & 127;         // float4 group within row
    const float* W = (j < 64) ? &Wv[j*INDIM] :
                     (j < 128) ? &Wk[(j-64)*INDIM] : &Wa[(j-128)*INDIM];
    float4 wv = *(const float4*)&W[q*4];
    uint32_t h01 = cvt_bf16x2(wv.x, wv.y);
    uint32_t h23 = cvt_bf16x2(wv.z, wv.w);
    float f0 = __uint_as_float(h01 << 16);
    float f1 = __uint_as_float(h01 & 0xFFFF0000u);
    float f2 = __uint_as_float(h23 << 16);
    float f3 = __uint_as_float(h23 & 0xFFFF0000u);
    uint32_t l01 = cvt_bf16x2(wv.x - f0, wv.y - f1);
    uint32_t l23 = cvt_bf16x2(wv.z - f2, wv.w - f3);
    *(uint2*)&g_Wh[j*INDIM + q*4] = make_uint2(h01, h23);
    *(uint2*)&g_Wl[j*INDIM + q*4] = make_uint2(l01, l23);
}

// ---------------- K1: mma.sync bf16-split projection GEMM ---------------------
// 128 CTAs x 256 threads; M-tile 64 rows. Warp (mw = wid&3, nw = wid>>2):
// rows mw*16..+15, cols nw*96..+95 (12 n-tiles). Full-chip coverage.
#define KC   64
#define NCHK (INDIM/KC)     // 8
#define SA   72             // bf16 row stride (36 words == 4 mod 32: conflict-free frags)
#define OFF_AH   0
#define OFF_AL   9216       // 64*72*2
#define OFF_BH   18432
#define OFF_BL   46080      // +192*72*2
#define OFF_BIAS 73728
#define SMEM_PROJ (73728 + 192*4)

__global__ void __launch_bounds__(256) proj_mma(
    const float* __restrict__ x,
    const float* __restrict__ bv, const float* __restrict__ bk, const float* __restrict__ ba)
{
    extern __shared__ char smem[];
    uint16_t* sAH = (uint16_t*)(smem + OFF_AH);
    uint16_t* sAL = (uint16_t*)(smem + OFF_AL);
    uint16_t* sBH = (uint16_t*)(smem + OFF_BH);
    uint16_t* sBL = (uint16_t*)(smem + OFF_BL);
    float*  sBias = (float*)(smem + OFF_BIAS);

    int tid = threadIdx.x;
    int wid = tid >> 5, lid = tid & 31;
    int g = lid >> 2, t = lid & 3;
    int mw = wid & 3, nw = wid >> 2;
    int mb = blockIdx.x * 64;
    if (tid < NOUT)
        sBias[tid] = (tid < 64) ? bv[tid] : ((tid < 128) ? bk[tid-64] : ba[tid-128]);

    float c[12][4];
    #pragma unroll
    for (int j = 0; j < 12; j++)
        #pragma unroll
        for (int q = 0; q < 4; q++) c[j][q] = 0.0f;

    for (int ch = 0; ch < NCHK; ch++){
        int kk = ch * KC;
        // ---- A fill (convert): 64 rows x 16 float4 (4 iters/thread) ----
        #pragma unroll
        for (int it = 0; it < 4; it++){
            int i = tid + it*256;
            int row = i >> 4, q = i & 15;
            float4 xv = *(const float4*)&x[(mb + row)*INDIM + kk + q*4];
            uint32_t h01 = cvt_bf16x2(xv.x, xv.y);
            uint32_t h23 = cvt_bf16x2(xv.z, xv.w);
            float f0 = __uint_as_float(h01 << 16);
            float f1 = __uint_as_float(h01 & 0xFFFF0000u);
            float f2 = __uint_as_float(h23 << 16);
            float f3 = __uint_as_float(h23 & 0xFFFF0000u);
            uint32_t l01 = cvt_bf16x2(xv.x - f0, xv.y - f1);
            uint32_t l23 = cvt_bf16x2(xv.z - f2, xv.w - f3);
            int off = row*SA + q*4;
            *(uint2*)&sAH[off] = make_uint2(h01, h23);
            *(uint2*)&sAL[off] = make_uint2(l01, l23);
        }
        // ---- B fill (pure copy of precomputed bf16): 192 rows x 8 uint4 ----
        #pragma unroll
        for (int it = 0; it < 6; it++){
            int i = tid + it*256;     // 0..1535
            int row = i >> 3, q = i & 7;
            uint4 h = *(const uint4*)&g_Wh[row*INDIM + kk + q*8];
            uint4 l = *(const uint4*)&g_Wl[row*INDIM + kk + q*8];
            *(uint4*)&sBH[row*SA + q*8] = h;
            *(uint4*)&sBL[row*SA + q*8] = l;
        }
        __syncthreads();
        // ---- MMA: 4 K=16 steps, 12 n-tiles, 3 split products each ----
        #pragma unroll
        for (int ks = 0; ks < 4; ks++){
            int ak = ks*16;
            int ra = (mw*16 + g)*SA + ak + 2*t;
            uint32_t aH[4], aL[4];
            aH[0] = *(const uint32_t*)&sAH[ra];
            aH[1] = *(const uint32_t*)&sAH[ra + 8*SA];
            aH[2] = *(const uint32_t*)&sAH[ra + 8];
            aH[3] = *(const uint32_t*)&sAH[ra + 8*SA + 8];
            aL[0] = *(const uint32_t*)&sAL[ra];
            aL[1] = *(const uint32_t*)&sAL[ra + 8*SA];
            aL[2] = *(const uint32_t*)&sAL[ra + 8];
            aL[3] = *(const uint32_t*)&sAL[ra + 8*SA + 8];
            #pragma unroll
            for (int j = 0; j < 12; j++){
                int jj = nw*12 + j;
                int rb = (jj*8 + g)*SA + ak + 2*t;
                uint32_t bH0 = *(const uint32_t*)&sBH[rb];
                uint32_t bH1 = *(const uint32_t*)&sBH[rb + 8];
                uint32_t bL0 = *(const uint32_t*)&sBL[rb];
                uint32_t bL1 = *(const uint32_t*)&sBL[rb + 8];
                mma16816(c[j], aH, bH0, bH1);
                mma16816(c[j], aH, bL0, bL1);
                mma16816(c[j], aL, bH0, bH1);
            }
        }
        __syncthreads();
    }

    // ---- epilogue: bias + routing ----
    int row0 = mb + mw*16 + g;
    #pragma unroll
    for (int j = 0; j < 12; j++){
        int jj = nw*12 + j;
        float b0 = sBias[jj*8 + 2*t];
        float b1 = sBias[jj*8 + 2*t + 1];
        float v00 = c[j][0] + b0, v01 = c[j][1] + b1;    // row0
        float v10 = c[j][2] + b0, v11 = c[j][3] + b1;    // row0+8
        int col = (jj & 7)*8 + 2*t;
        if (jj < 8){
            *(float2*)&g_v[row0*64 + col]     = make_float2(v00, v01);
            *(float2*)&g_v[(row0+8)*64 + col] = make_float2(v10, v11);
        } else if (jj < 16){
            *(float2*)&g_k[row0*64 + col]     = make_float2(v00, v01);
            *(float2*)&g_k[(row0+8)*64 + col] = make_float2(v10, v11);
        } else {
            float s00 = fmaxf(fminf(v00,0.0f) - log1pf(expf(-fabsf(v00))), LOG_EPS);
            float s01 = fmaxf(fminf(v01,0.0f) - log1pf(expf(-fabsf(v01))), LOG_EPS);
            float s10 = fmaxf(fminf(v10,0.0f) - log1pf(expf(-fabsf(v10))), LOG_EPS);
            float s11 = fmaxf(fminf(v11,0.0f) - log1pf(expf(-fabsf(v11))), LOG_EPS);
            *(float2*)&g_la[row0*64 + col]     = make_float2(s00, s01);
            *(float2*)&g_la[(row0+8)*64 + col] = make_float2(s10, s11);
        }
    }
}

// ---------------- K2: fused chunk sums + exclusive prefix (coalesced) ---------
__global__ void __launch_bounds__(1024) la_scan(){
    __shared__ float tile[32][33];
    int lane = threadIdx.x & 31;
    int wid  = threadIdx.x >> 5;
    int bnBase = blockIdx.x * 32;
    int myBn = bnBase + wid;
    float carry = 0.0f;
    #pragma unroll
    for (int pass = 0; pass < NCH/32; pass++){
        int c = pass*32 + wid;
        const float* p = g_la + c*TCHK*512 + bnBase + lane;
        float s = 0.0f;
        #pragma unroll
        for (int i = 0; i < TCHK; i++) s += p[i*512];
        tile[wid][lane] = s;
        __syncthreads();
        float v = tile[lane][wid];
        float sc = v;
        #pragma unroll
        for (int off = 1; off < 32; off <<= 1){
            float t = __shfl_up_sync(0xffffffffu, sc, off);
            if (lane >= off) sc += t;
        }
        float ex = __shfl_up_sync(0xffffffffu, sc, 1);
        if (lane == 0) ex = 0.0f;
        float tot = __shfl_sync(0xffffffffu, sc, 31);
        __syncthreads();
        tile[lane][wid] = carry + ex;
        carry += tot;
        __syncthreads();
        g_carry[(pass*32 + wid)*512 + bnBase + lane] = tile[wid][lane];
        __syncthreads();
    }
    if (lane == 31) g_inv[myBn] = 1.0f / (expf(carry) + 1e-8f);
}

// ---------------- shared fill: v tile + computed kd tile ----------------------
__device__ __forceinline__ void fill_tiles(float* s_v, float* s_kd, int seg, int b, int tid){
    #pragma unroll
    for (int i = tid; i < SEGT*16; i += 256){
        int t = i >> 4, q = i & 15;
        int row = ((seg*SEGT + t)*B_DIM + b)*64;
        ((float4*)s_v)[i] = *(const float4*)&g_v[row + q*4];
    }
    {
        int n  = tid & 63;
        int cl = tid >> 6;
        int c  = seg*4 + cl;
        int bn = b*64 + n;
        float cum = g_carry[c*512 + bn];
        float inv = g_inv[bn];
        #pragma unroll
        for (int i = 0; i < TCHK; i++){
            int t = cl*TCHK + i;
            int addr = ((seg*SEGT + t)*B_DIM + b)*64 + n;
            cum += g_la[addr];
            float dec = expf(cum) * inv;
            s_kd[t*64 + n] = g_k[addr] * dec;
        }
    }
    __syncthreads();
}

// ---------------- K4: per-segment outer-product sums ----------
__global__ void __launch_bounds__(256) seg_sums(){
    int seg = blockIdx.x, b = blockIdx.y;
    __shared__ float s_v[SEGT*64];
    __shared__ float s_kd[SEGT*64];
    int tid = threadIdx.x;
    fill_tiles(s_v, s_kd, seg, b, tid);
    int dq = tid >> 4, n4 = tid & 15;
    float4 a0 = {0,0,0,0}, a1 = {0,0,0,0}, a2 = {0,0,0,0}, a3 = {0,0,0,0};
    #pragma unroll 4
    for (int t = 0; t < SEGT; t++){
        float4 kd = *(const float4*)&s_kd[t*64 + n4*4];
        float4 vv = *(const float4*)&s_v [t*64 + dq*4];
        a0.x = fmaf(vv.x, kd.x, a0.x); a0.y = fmaf(vv.x, kd.y, a0.y);
        a0.z = fmaf(vv.x, kd.z, a0.z); a0.w = fmaf(vv.x, kd.w, a0.w);
        a1.x = fmaf(vv.y, kd.x, a1.x); a1.y = fmaf(vv.y, kd.y, a1.y);
        a1.z = fmaf(vv.y, kd.z, a1.z); a1.w = fmaf(vv.y, kd.w, a1.w);
        a2.x = fmaf(vv.z, kd.x, a2.x); a2.y = fmaf(vv.z, kd.y, a2.y);
        a2.z = fmaf(vv.z, kd.z, a2.z); a2.w = fmaf(vv.z, kd.w, a2.w);
        a3.x = fmaf(vv.w, kd.x, a3.x); a3.y = fmaf(vv.w, kd.y, a3.y);
        a3.z = fmaf(vv.w, kd.z, a3.z); a3.w = fmaf(vv.w, kd.w, a3.w);
    }
    float* P = g_P + (seg*B_DIM + b)*4096;
    *(float4*)&P[(dq*4+0)*64 + n4*4] = a0;
    *(float4*)&P[(dq*4+1)*64 + n4*4] = a1;
    *(float4*)&P[(dq*4+2)*64 + n4*4] = a2;
    *(float4*)&P[(dq*4+3)*64 + n4*4] = a3;
}

// ---------------- K4b: exclusive prefix of P along seg (register scan) --------
__global__ void __launch_bounds__(256) seg_prefix(){
    int idx = blockIdx.x*256 + threadIdx.x;   // 0..32767
    float v[NSEG];
    #pragma unroll
    for (int s = 0; s < NSEG; s++) v[s] = g_P[s*32768 + idx];
    float carry = 0.0f;
    #pragma unroll
    for (int s = 0; s < NSEG; s++){
        float t = v[s];
        v[s] = carry;
        carry += t;
    }
    #pragma unroll
    for (int s = 0; s < NSEG; s++) g_P[s*32768 + idx] = v[s];
}

// ---------------- K5: scan + store (128 MB) ---------------------
__global__ void __launch_bounds__(256) scan_kernel(float* __restrict__ out){
    int seg = blockIdx.x, b = blockIdx.y;
    __shared__ float s_v[SEGT*64];
    __shared__ float s_kd[SEGT*64];
    int tid = threadIdx.x;
    fill_tiles(s_v, s_kd, seg, b, tid);
    int dq = tid >> 4, n4 = tid & 15;
    const float* P = g_P + (seg*B_DIM + b)*4096;
    float4 a0 = *(const float4*)&P[(dq*4+0)*64 + n4*4];
    float4 a1 = *(const float4*)&P[(dq*4+1)*64 + n4*4];
    float4 a2 = *(const float4*)&P[(dq*4+2)*64 + n4*4];
    float4 a3 = *(const float4*)&P[(dq*4+3)*64 + n4*4];
    #pragma unroll 4
    for (int t = 0; t < SEGT; t++){
        float4 kd = *(const float4*)&s_kd[t*64 + n4*4];
        float4 vv = *(const float4*)&s_v [t*64 + dq*4];
        a0.x = fmaf(vv.x, kd.x, a0.x); a0.y = fmaf(vv.x, kd.y, a0.y);
        a0.z = fmaf(vv.x, kd.z, a0.z); a0.w = fmaf(vv.x, kd.w, a0.w);
        a1.x = fmaf(vv.y, kd.x, a1.x); a1.y = fmaf(vv.y, kd.y, a1.y);
        a1.z = fmaf(vv.y, kd.z, a1.z); a1.w = fmaf(vv.y, kd.w, a1.w);
        a2.x = fmaf(vv.z, kd.x, a2.x); a2.y = fmaf(vv.z, kd.y, a2.y);
        a2.z = fmaf(vv.z, kd.z, a2.z); a2.w = fmaf(vv.z, kd.w, a2.w);
        a3.x = fmaf(vv.w, kd.x, a3.x); a3.y = fmaf(vv.w, kd.y, a3.y);
        a3.z = fmaf(vv.w, kd.z, a3.z); a3.w = fmaf(vv.w, kd.w, a3.w);
        float* orow = out + (size_t)((seg*SEGT + t)*B_DIM + b)*4096;
        *(float4*)&orow[(dq*4+0)*64 + n4*4] = a0;
        *(float4*)&orow[(dq*4+1)*64 + n4*4] = a1;
        *(float4*)&orow[(dq*4+2)*64 + n4*4] = a2;
        *(float4*)&orow[(dq*4+3)*64 + n4*4] = a3;
    }
}

// ---------------- launch ----------------
extern "C" void kernel_launch(void* const* d_in, const int* in_sizes, int n_in,
                              void* d_out, int out_size){
    const float* x  = (const float*)d_in[0];
    const float* Wv = (const float*)d_in[1];
    const float* bv = (const float*)d_in[2];
    const float* Wk = (const float*)d_in[3];
    const float* bk = (const float*)d_in[4];
    const float* Wa = (const float*)d_in[5];
    const float* ba = (const float*)d_in[6];
    float* out = (float*)d_out;

    static int attr_set = 0;
    if (!attr_set){
        cudaFuncSetAttribute(proj_mma, cudaFuncAttributeMaxDynamicSharedMemorySize, SMEM_PROJ);
        attr_set = 1;
    }
    pack_w<<<96, 256>>>(Wv, Wk, Wa);
    proj_mma<<<M_TOT/64, 256, SMEM_PROJ>>>(x, bv, bk, ba);
    la_scan<<<16, 1024>>>();
    dim3 gseg(NSEG, B_DIM);
    seg_sums<<<gseg, 256>>>();
    seg_prefix<<<128, 256>>>();
    scan_kernel<<<gseg, 256>>>(out);
}